// round 5
// baseline (speedup 1.0000x reference)
#include <cuda_runtime.h>
#include <cstdint>

// exp(X) for batched 32x32 symmetric fp32: scaling-and-squaring + degree-8
// Paterson-Stockmeyer Taylor. Two matrices per warp (half-warp h owns matrix h,
// lane owns columns jj, jj+16). Matmuls run as TWO half-passes over output rows
// (acc = 32 regs); B-operand columns live in registers (reloaded once per mm);
// results stream to smem columns. All operands are symmetric (polynomials in X)
// so the row-major read computes A^T*B = A*B. Two smem buffers:
//   A: X -> Xs -> B0 -> P(ping)        E: X2 -> Z -> P(pong)

#define STRIDE 36               // floats per smem row
#define ROWB   144              // bytes per smem row
#define MOFF   1168             // matrix-1 word offset (+16-bank shift)
#define BUFF   2320             // floats per buffer (2 matrices)

typedef unsigned long long u64;

static __device__ __forceinline__ u64 pk2(float v) {
    u64 r; asm("mov.b64 %0, {%1, %1};" : "=l"(r) : "f"(v)); return r;
}
static __device__ __forceinline__ void upk2(float& lo, float& hi, u64 v) {
    asm("mov.b64 {%0, %1}, %2;" : "=f"(lo), "=f"(hi) : "l"(v));
}
static __device__ __forceinline__ void fma2(u64& d, u64 a, u64 b) {
    asm("fma.rn.f32x2 %0, %1, %2, %0;" : "+l"(d) : "l"(a), "l"(b));
}
static __device__ __forceinline__ u64 mul2(u64 a, u64 b) {
    u64 d; asm("mul.rn.f32x2 %0, %1, %2;" : "=l"(d) : "l"(a), "l"(b)); return d;
}
static __device__ __forceinline__ float ldsf(uint32_t a) {
    float f; asm volatile("ld.shared.f32 %0, [%1];" : "=f"(f) : "r"(a)); return f;
}
static __device__ __forceinline__ void stsf(uint32_t a, float f) {
    asm volatile("st.shared.f32 [%0], %1;" :: "r"(a), "f"(f));
}

// Half-pass: rows [half*16, half*16+16) of C(:,c0) and C(:,c1).
// A rows broadcast from smem (LDS.128; the two half-warps hit bank-disjoint
// 16B chunks), B columns in registers.
static __device__ __forceinline__ void mmh(uint32_t aBase, int half,
                                           const float* b0, const float* b1,
                                           u64 acc0[8], u64 acc1[8]) {
    const uint32_t base = aBase + (uint32_t)(half * 64);
    {   // k = 0 peeled: mul (no zero-init MOVs)
        u64 bb0 = pk2(b0[0]), bb1 = pk2(b1[0]);
#pragma unroll
        for (int q = 0; q < 4; ++q) {
            u64 a0, a1;
            asm volatile("ld.shared.v2.u64 {%0, %1}, [%2];"
                         : "=l"(a0), "=l"(a1) : "r"(base + (uint32_t)(q * 16)));
            acc0[2 * q]     = mul2(a0, bb0);
            acc0[2 * q + 1] = mul2(a1, bb0);
            acc1[2 * q]     = mul2(a0, bb1);
            acc1[2 * q + 1] = mul2(a1, bb1);
        }
    }
#pragma unroll
    for (int k = 1; k < 32; ++k) {
        u64 bb0 = pk2(b0[k]), bb1 = pk2(b1[k]);
        const uint32_t ra = base + (uint32_t)(k * ROWB);
#pragma unroll
        for (int q = 0; q < 4; ++q) {
            u64 a0, a1;
            asm volatile("ld.shared.v2.u64 {%0, %1}, [%2];"
                         : "=l"(a0), "=l"(a1) : "r"(ra + (uint32_t)(q * 16)));
            fma2(acc0[2 * q],     a0, bb0);
            fma2(acc0[2 * q + 1], a1, bb0);
            fma2(acc1[2 * q],     a0, bb1);
            fma2(acc1[2 * q + 1], a1, bb1);
        }
    }
}

__global__ void __launch_bounds__(32, 12)
ExpEig_52553219834314_kernel(const float* __restrict__ in,
                             float* __restrict__ out, int B) {
    __shared__ __align__(16) float smem[2 * BUFF];

    const int lane = threadIdx.x;
    const int h = lane >> 4, jj = lane & 15;
    int mat = blockIdx.x * 2 + h;
    const bool alive = (mat < B);
    if (!alive) mat = B - 1;
    const int c0 = jj, c1 = jj + 16;

    const uint32_t aA = (uint32_t)__cvta_generic_to_shared(smem)
                      + (uint32_t)(h * MOFF * 4);
    const uint32_t aE = aA + (uint32_t)(BUFF * 4);
    const uint32_t Ac0 = aA + (uint32_t)(c0 * 4), Ac1 = aA + (uint32_t)(c1 * 4);
    const uint32_t Ec0 = aE + (uint32_t)(c0 * 4), Ec1 = aE + (uint32_t)(c1 * 4);

    float b0[32], b1[32];
    {
        const float* src = in + (size_t)mat * 1024;
#pragma unroll
        for (int i = 0; i < 32; ++i) {
            b0[i] = src[i * 32 + c0];
            b1[i] = src[i * 32 + c1];
        }
#pragma unroll
        for (int i = 0; i < 32; ++i) {
            stsf(Ac0 + (uint32_t)(i * ROWB), b0[i]);
            stsf(Ac1 + (uint32_t)(i * ROWB), b1[i]);
        }
    }
    __syncwarp();

    u64 acc0[8], acc1[8];
    float ra0 = 0.f, ra1 = 0.f, fb = 0.f;

    // ---- stage 0: X2 = X*X -> E columns; bound sums on the fly
#pragma unroll
    for (int half = 0; half < 2; ++half) {
        mmh(aA, half, b0, b1, acc0, acc1);
#pragma unroll
        for (int p = 0; p < 8; ++p) {
            float v0, v1, w0, w1;
            upk2(v0, v1, acc0[p]); upk2(w0, w1, acc1[p]);
            ra0 += fabsf(v0) + fabsf(v1);
            ra1 += fabsf(w0) + fabsf(w1);
            fb  += v0 * v0 + v1 * v1 + w0 * w0 + w1 * w1;
            const int i = half * 16 + 2 * p;
            stsf(Ec0 + (uint32_t)(i * ROWB), v0);
            stsf(Ec0 + (uint32_t)((i + 1) * ROWB), v1);
            stsf(Ec1 + (uint32_t)(i * ROWB), w0);
            stsf(Ec1 + (uint32_t)((i + 1) * ROWB), w1);
        }
    }

    // Spectral bound: ||X||_2 <= sqrt(min(||X2||_1, ||X2||_F)).
    float rs = fmaxf(ra0, ra1);
#pragma unroll
    for (int off = 8; off > 0; off >>= 1) {
        rs = fmaxf(rs, __shfl_xor_sync(0xffffffffu, rs, off));
        fb += __shfl_xor_sync(0xffffffffu, fb, off);
    }
    float bnd = sqrtf(fminf(rs, sqrtf(fb)));
    bnd = fmaxf(bnd, __shfl_xor_sync(0xffffffffu, bnd, 16));
    int e = 0; (void)frexpf(bnd, &e);
    const int kk = e < 0 ? 0 : (e > 24 ? 24 : e);
    const int total = 4 + kk;
    const float s1f = exp2f(-(float)kk), s2f = s1f * s1f;

    __syncwarp();           // stage-0 cross-lane row reads of A complete
    // A := Xs (in-place column scale);  b := X2s (read back own E columns).
#pragma unroll
    for (int i = 0; i < 32; ++i) {
        stsf(Ac0 + (uint32_t)(i * ROWB), s1f * ldsf(Ac0 + (uint32_t)(i * ROWB)));
        stsf(Ac1 + (uint32_t)(i * ROWB), s1f * ldsf(Ac1 + (uint32_t)(i * ROWB)));
        b0[i] = s2f * ldsf(Ec0 + (uint32_t)(i * ROWB));
        b1[i] = s2f * ldsf(Ec1 + (uint32_t)(i * ROWB));
    }
    __syncwarp();           // Xs visible for cross-lane row reads

    // ---- stage 1: Z = Xs * X2s -> E
#pragma unroll
    for (int half = 0; half < 2; ++half) {
        mmh(aA, half, b0, b1, acc0, acc1);
#pragma unroll
        for (int p = 0; p < 8; ++p) {
            float v0, v1, w0, w1;
            upk2(v0, v1, acc0[p]); upk2(w0, w1, acc1[p]);
            const int i = half * 16 + 2 * p;
            stsf(Ec0 + (uint32_t)(i * ROWB), v0);
            stsf(Ec0 + (uint32_t)((i + 1) * ROWB), v1);
            stsf(Ec1 + (uint32_t)(i * ROWB), w0);
            stsf(Ec1 + (uint32_t)((i + 1) * ROWB), w1);
        }
    }
    __syncwarp();           // Z visible; all row reads of A(Xs) done

    // epilogue 1: A := B0 = I + Xs + X2s/2 ;  b := B2 = I/720 + Xs/5040 + X2s/40320
#pragma unroll
    for (int i = 0; i < 32; ++i) {
        float xs0 = ldsf(Ac0 + (uint32_t)(i * ROWB));
        float xs1 = ldsf(Ac1 + (uint32_t)(i * ROWB));
        float kr0 = (i == c0) ? 1.f : 0.f, kr1 = (i == c1) ? 1.f : 0.f;
        stsf(Ac0 + (uint32_t)(i * ROWB), kr0 + xs0 + 0.5f * b0[i]);
        stsf(Ac1 + (uint32_t)(i * ROWB), kr1 + xs1 + 0.5f * b1[i]);
        b0[i] = kr0 * (1.f / 720.f) + xs0 * (1.f / 5040.f) + b0[i] * (1.f / 40320.f);
        b1[i] = kr1 * (1.f / 720.f) + xs1 * (1.f / 5040.f) + b1[i] * (1.f / 40320.f);
    }
    // A writes lane-private, E stable -> no sync needed before stage 2.

    // ---- stage 2: U = Z * B2 ;  b := V = U + 168*B2 - 0.075*I + B0/120
    {
        u64 sac0[8], sac1[8];
        mmh(aE, 0, b0, b1, sac0, sac1);
        mmh(aE, 1, b0, b1, acc0, acc1);
#pragma unroll
        for (int p = 0; p < 8; ++p) {
            float u0, u1, w0, w1;
            upk2(u0, u1, sac0[p]); upk2(w0, w1, sac1[p]);
            int i = 2 * p;
            b0[i]     = u0 + 168.f * b0[i]     - 0.075f * ((i == c0) ? 1.f : 0.f)
                      + ldsf(Ac0 + (uint32_t)(i * ROWB)) * (1.f / 120.f);
            b0[i + 1] = u1 + 168.f * b0[i + 1] - 0.075f * ((i + 1 == c0) ? 1.f : 0.f)
                      + ldsf(Ac0 + (uint32_t)((i + 1) * ROWB)) * (1.f / 120.f);
            b1[i]     = w0 + 168.f * b1[i]     - 0.075f * ((i == c1) ? 1.f : 0.f)
                      + ldsf(Ac1 + (uint32_t)(i * ROWB)) * (1.f / 120.f);
            b1[i + 1] = w1 + 168.f * b1[i + 1] - 0.075f * ((i + 1 == c1) ? 1.f : 0.f)
                      + ldsf(Ac1 + (uint32_t)((i + 1) * ROWB)) * (1.f / 120.f);
            upk2(u0, u1, acc0[p]); upk2(w0, w1, acc1[p]);
            i = 16 + 2 * p;
            b0[i]     = u0 + 168.f * b0[i]     - 0.075f * ((i == c0) ? 1.f : 0.f)
                      + ldsf(Ac0 + (uint32_t)(i * ROWB)) * (1.f / 120.f);
            b0[i + 1] = u1 + 168.f * b0[i + 1] - 0.075f * ((i + 1 == c0) ? 1.f : 0.f)
                      + ldsf(Ac0 + (uint32_t)((i + 1) * ROWB)) * (1.f / 120.f);
            b1[i]     = w0 + 168.f * b1[i]     - 0.075f * ((i == c1) ? 1.f : 0.f)
                      + ldsf(Ac1 + (uint32_t)(i * ROWB)) * (1.f / 120.f);
            b1[i + 1] = w1 + 168.f * b1[i + 1] - 0.075f * ((i + 1 == c1) ? 1.f : 0.f)
                      + ldsf(Ac1 + (uint32_t)((i + 1) * ROWB)) * (1.f / 120.f);
        }
    }

    // ---- stage 3: M = Z * V ;  P = M + B0 -> A (or gmem when total==4)
    float* dst = out + (size_t)mat * 1024;
#pragma unroll
    for (int half = 0; half < 2; ++half) {
        mmh(aE, half, b0, b1, acc0, acc1);
#pragma unroll
        for (int p = 0; p < 8; ++p) {
            float v0, v1, w0, w1;
            upk2(v0, v1, acc0[p]); upk2(w0, w1, acc1[p]);
            const int i = half * 16 + 2 * p;
            float p00 = v0 + ldsf(Ac0 + (uint32_t)(i * ROWB));
            float p01 = v1 + ldsf(Ac0 + (uint32_t)((i + 1) * ROWB));
            float p10 = w0 + ldsf(Ac1 + (uint32_t)(i * ROWB));
            float p11 = w1 + ldsf(Ac1 + (uint32_t)((i + 1) * ROWB));
            if (total == 4) {
                if (alive) {
                    dst[i * 32 + c0] = p00; dst[(i + 1) * 32 + c0] = p01;
                    dst[i * 32 + c1] = p10; dst[(i + 1) * 32 + c1] = p11;
                }
            } else {
                stsf(Ac0 + (uint32_t)(i * ROWB), p00);
                stsf(Ac0 + (uint32_t)((i + 1) * ROWB), p01);
                stsf(Ac1 + (uint32_t)(i * ROWB), p10);
                stsf(Ac1 + (uint32_t)((i + 1) * ROWB), p11);
            }
        }
    }
    __syncwarp();

    // ---- squarings: P = P*P, ping-pong A <-> E
    uint32_t ping = aA, pc0 = Ac0, pc1 = Ac1;
    uint32_t qn = aE, qc0 = Ec0, qc1 = Ec1;
    for (int s = 4; s < total; ++s) {
        const bool last = (s == total - 1);
#pragma unroll
        for (int i = 0; i < 32; ++i) {     // b := P columns (own writes)
            b0[i] = ldsf(pc0 + (uint32_t)(i * ROWB));
            b1[i] = ldsf(pc1 + (uint32_t)(i * ROWB));
        }
#pragma unroll
        for (int half = 0; half < 2; ++half) {
            mmh(ping, half, b0, b1, acc0, acc1);
#pragma unroll
            for (int p = 0; p < 8; ++p) {
                float v0, v1, w0, w1;
                upk2(v0, v1, acc0[p]); upk2(w0, w1, acc1[p]);
                const int i = half * 16 + 2 * p;
                if (last) {
                    if (alive) {
                        dst[i * 32 + c0] = v0; dst[(i + 1) * 32 + c0] = v1;
                        dst[i * 32 + c1] = w0; dst[(i + 1) * 32 + c1] = w1;
                    }
                } else {
                    stsf(qc0 + (uint32_t)(i * ROWB), v0);
                    stsf(qc0 + (uint32_t)((i + 1) * ROWB), v1);
                    stsf(qc1 + (uint32_t)(i * ROWB), w0);
                    stsf(qc1 + (uint32_t)((i + 1) * ROWB), w1);
                }
            }
        }
        __syncwarp();
        uint32_t t;
        t = ping; ping = qn;  qn = t;
        t = pc0;  pc0 = qc0;  qc0 = t;
        t = pc1;  pc1 = qc1;  qc1 = t;
    }
}

extern "C" void kernel_launch(void* const* d_in, const int* in_sizes, int n_in,
                              void* d_out, int out_size) {
    (void)n_in; (void)out_size;
    const float* x = (const float*)d_in[0];
    float* out = (float*)d_out;
    const int B = in_sizes[0] / 1024;
    const int ctas = (B + 1) / 2;
    ExpEig_52553219834314_kernel<<<ctas, 32>>>(x, out, B);
}